// round 1
// baseline (speedup 1.0000x reference)
#include <cuda_runtime.h>
#include <math_constants.h>

// Problem constants (fixed by setup_inputs): B=2, H=W=64.
// grid_dist_tensor: [H,W,64,64] -> 4096 tiles of 4096 contiguous floats.
// Outputs concatenated: loss[2,64,64], min_dist[2,64,64], min_dist_inv[2,64,64].

#define EPS_F   1e-8f
#define BIG_F   1000000.0f
#define HW      4096      // 64*64
#define BHW     8192      // 2*64*64

__global__ __launch_bounds__(256, 8)
void project_loss_kernel(const float* __restrict__ preds,
                         const float* __restrict__ gts,
                         const float* __restrict__ grid,
                         float* __restrict__ out)
{
    const int tile = blockIdx.x;          // hw index, 0..4095
    const int tid  = threadIdx.x;         // 256 threads

    // --- per-tile min over 4096 floats, float4 vectorized ---
    const float4* g4 = reinterpret_cast<const float4*>(grid + (size_t)tile * HW);

    // Front-batch the 4 loads for MLP
    float4 v0 = g4[tid];
    float4 v1 = g4[tid + 256];
    float4 v2 = g4[tid + 512];
    float4 v3 = g4[tid + 768];

    float m = fminf(fminf(v0.x, v0.y), fminf(v0.z, v0.w));
    m = fminf(m, fminf(fminf(v1.x, v1.y), fminf(v1.z, v1.w)));
    m = fminf(m, fminf(fminf(v2.x, v2.y), fminf(v2.z, v2.w)));
    m = fminf(m, fminf(fminf(v3.x, v3.y), fminf(v3.z, v3.w)));

    // warp reduce
    #pragma unroll
    for (int o = 16; o > 0; o >>= 1)
        m = fminf(m, __shfl_xor_sync(0xFFFFFFFFu, m, o));

    __shared__ float smin[8];
    if ((tid & 31) == 0) smin[tid >> 5] = m;
    __syncthreads();

    // threads 0 and 1 handle batch b = tid
    if (tid < 2) {
        float mm = smin[0];
        #pragma unroll
        for (int i = 1; i < 8; i++) mm = fminf(mm, smin[i]);
        const float dist = mm + 1.0f;      // min over (grid+1) == min(grid)+1

        const int b   = tid;
        const int idx = b * HW + tile;     // index into [B,H,W] flattened

        const float p = preds[idx];
        const float g = gts[idx];

        // bce_prob loss
        const float loss = -g * logf(p + EPS_F)
                           - (1.0f - g) * logf(fabsf(1.0f - p - EPS_F));

        const float pred_mask = p + (1.0f - p) * BIG_F;
        const float gt_th     = g + (1.0f - g) * BIG_F;

        out[idx]            = loss;                      // loss
        out[BHW + idx]      = gt_th * dist * p;          // min_dist
        out[2 * BHW + idx]  = g * dist * pred_mask;      // min_dist_inv
    }
}

extern "C" void kernel_launch(void* const* d_in, const int* in_sizes, int n_in,
                              void* d_out, int out_size)
{
    const float* preds = (const float*)d_in[0];
    const float* gts   = (const float*)d_in[1];
    const float* grid  = (const float*)d_in[2];
    float* out = (float*)d_out;

    project_loss_kernel<<<HW, 256>>>(preds, gts, grid, out);
}